// round 14
// baseline (speedup 1.0000x reference)
#include <cuda_runtime.h>
#include <cuda_bf16.h>
#include <math.h>

#define KC 8192
#define DD 128
#define NR 8192
#define NT 32            // 128-code tiles per half codebook
#define MARGIN 0.004f

typedef unsigned long long ull;
typedef unsigned int u32;

// ---- global scratch (static, no allocations) ----
__device__ float g_qc[KC * DD];
__device__ float g_cnorm[KC];
__device__ float g_zn[NR];
__device__ float g_counts[KC];
__device__ float g_commit;
__device__ int   g_candn[NR];
__device__ int   g_cand[NR * 64];
__device__ int   g_over[NR];
__device__ int   g_idx[NR];
// linear bf16 hi/lo operands, row-major [8192][128]
__device__ __nv_bfloat162 g_zh[NR * 64];
__device__ __nv_bfloat162 g_zl[NR * 64];
__device__ __nv_bfloat162 g_ch[KC * 64];
__device__ __nv_bfloat162 g_cl[KC * 64];

extern __shared__ char smem_raw[];

// ---- asm helpers (sm_80-era, compile at compute_100) ----
static __device__ __forceinline__ void cp_commit() {
    asm volatile("cp.async.commit_group;");
}
static __device__ __forceinline__ void cp_wait0() {
    asm volatile("cp.async.wait_group 0;");
}
#define LDSM4(r, addr) \
    asm volatile("ldmatrix.sync.aligned.m8n8.x4.shared.b16 {%0,%1,%2,%3}, [%4];" \
        : "=r"((r)[0]), "=r"((r)[1]), "=r"((r)[2]), "=r"((r)[3]) : "r"(addr))
#define MMA16816(c, a, b0, b1) \
    asm volatile("mma.sync.aligned.m16n8k16.row.col.f32.bf16.bf16.f32 " \
        "{%0,%1,%2,%3},{%4,%5,%6,%7},{%8,%9},{%0,%1,%2,%3};" \
        : "+f"((c)[0]), "+f"((c)[1]), "+f"((c)[2]), "+f"((c)[3]) \
        : "r"((a)[0]), "r"((a)[1]), "r"((a)[2]), "r"((a)[3]), "r"(b0), "r"(b1))

// Copy one 32KB tile (128 rows x 256B) global->shared with chunk-XOR swizzle:
// 16B chunk c of row r lands at chunk (c ^ (r&7)) -> ldmatrix conflict-free.
static __device__ __forceinline__ void copy_tile(char* dst, const void* src, int tid) {
    u32 d = (u32)__cvta_generic_to_shared(dst);
    const char* s = (const char*)src;
#pragma unroll
    for (int i = 0; i < 8; i++) {
        int cid = tid + i * 256;
        u32 off = (u32)cid << 4;
        u32 row = off >> 8;
        u32 ch = (off >> 4) & 15u;
        u32 doff = (row << 8) | (((ch ^ (row & 7u)) & 15u) << 4);
        asm volatile("cp.async.cg.shared.global [%0], [%1], 16;"
                     :: "r"(d + doff), "l"(s + off));
    }
}

static __device__ __forceinline__ void split_store4(__nv_bfloat162* hb, __nv_bfloat162* lb,
                                                    int base2, float4 v) {
    __nv_bfloat16 h0 = __float2bfloat16(v.x), h1 = __float2bfloat16(v.y);
    __nv_bfloat16 h2 = __float2bfloat16(v.z), h3 = __float2bfloat16(v.w);
    __nv_bfloat162 hp0; hp0.x = h0; hp0.y = h1;
    __nv_bfloat162 hp1; hp1.x = h2; hp1.y = h3;
    __nv_bfloat162 lp0, lp1;
    lp0.x = __float2bfloat16(v.x - __bfloat162float(h0));
    lp0.y = __float2bfloat16(v.y - __bfloat162float(h1));
    lp1.x = __float2bfloat16(v.z - __bfloat162float(h2));
    lp1.y = __float2bfloat16(v.w - __bfloat162float(h3));
    hb[base2] = hp0; hb[base2 + 1] = hp1;
    lb[base2] = lp0; lb[base2 + 1] = lp1;
}

// ---------------------------------------------------------------------------
// k_prep: z -> bf16 hi/lo, exact fp32 row norms; zero per-run state.
// ---------------------------------------------------------------------------
__global__ __launch_bounds__(256) void k_prep(const float* __restrict__ z) {
    int row = blockIdx.x * 256 + threadIdx.x;
    g_candn[row] = 0; g_over[row] = 0; g_counts[row] = 0.f;
    if (row == 0) g_commit = 0.f;
    const float4* zr = (const float4*)(z + (size_t)row * DD);
    float s = 0.f;
#pragma unroll 8
    for (int i = 0; i < 32; i++) {
        float4 v = zr[i];
        s += v.x * v.x; s += v.y * v.y; s += v.z * v.z; s += v.w * v.w;
        split_store4(g_zh + row * 64, g_zl + row * 64, i * 2, v);
    }
    g_zn[row] = s;
}

// ---------------------------------------------------------------------------
// k_proj: qc = emb @ pw^T + pb ; cnorm ; bf16 hi/lo emit.
// ---------------------------------------------------------------------------
__global__ __launch_bounds__(256) void k_proj(const float* __restrict__ emb,
                                              const float* __restrict__ pw,
                                              const float* __restrict__ pb) {
    float* pwT = (float*)smem_raw;
    float* ebT = pwT + 16384;
    float* cn_s = ebT + 8192;
    const int tid = threadIdx.x;
    const int c0 = blockIdx.x * 64;
    if (tid < 64) cn_s[tid] = 0.f;
    {
        int n = tid & 127, h = tid >> 7;
        const float4* pr = (const float4*)(pw + (size_t)n * DD) + h * 16;
#pragma unroll
        for (int i = 0; i < 16; i++) {
            float4 v = pr[i];
            int k = (h * 16 + i) * 4;
            pwT[(k + 0) * 128 + n] = v.x; pwT[(k + 1) * 128 + n] = v.y;
            pwT[(k + 2) * 128 + n] = v.z; pwT[(k + 3) * 128 + n] = v.w;
        }
    }
    {
        int c = tid & 63, h = tid >> 6;
        const float4* er = (const float4*)(emb + (size_t)(c0 + c) * DD) + h * 8;
#pragma unroll
        for (int i = 0; i < 8; i++) {
            float4 v = er[i];
            int k = (h * 8 + i) * 4;
            ebT[(k + 0) * 64 + c] = v.x; ebT[(k + 1) * 64 + c] = v.y;
            ebT[(k + 2) * 64 + c] = v.z; ebT[(k + 3) * 64 + c] = v.w;
        }
    }
    __syncthreads();
    const int rg = tid >> 4, tc = tid & 15;
    float acc[4][8];
#pragma unroll
    for (int i = 0; i < 4; i++)
#pragma unroll
        for (int j = 0; j < 8; j++) acc[i][j] = 0.f;
#pragma unroll 4
    for (int k = 0; k < DD; k++) {
        float4 a = *(const float4*)(ebT + k * 64 + rg * 4);
        float4 b0 = *(const float4*)(pwT + k * 128 + tc * 4);
        float4 b1 = *(const float4*)(pwT + k * 128 + 64 + tc * 4);
        float av[4] = {a.x, a.y, a.z, a.w};
        float bv[8] = {b0.x, b0.y, b0.z, b0.w, b1.x, b1.y, b1.z, b1.w};
#pragma unroll
        for (int i = 0; i < 4; i++)
#pragma unroll
            for (int j = 0; j < 8; j++) acc[i][j] += av[i] * bv[j];
    }
    float pbv[8];
#pragma unroll
    for (int j = 0; j < 8; j++)
        pbv[j] = pb[(j < 4) ? (tc * 4 + j) : (64 + tc * 4 + (j - 4))];
#pragma unroll
    for (int i = 0; i < 4; i++) {
        int code = rg * 4 + i;
        float s = 0.f, v;
        float4 o0, o1;
        v = acc[i][0] + pbv[0]; o0.x = v; s += v * v;
        v = acc[i][1] + pbv[1]; o0.y = v; s += v * v;
        v = acc[i][2] + pbv[2]; o0.z = v; s += v * v;
        v = acc[i][3] + pbv[3]; o0.w = v; s += v * v;
        v = acc[i][4] + pbv[4]; o1.x = v; s += v * v;
        v = acc[i][5] + pbv[5]; o1.y = v; s += v * v;
        v = acc[i][6] + pbv[6]; o1.z = v; s += v * v;
        v = acc[i][7] + pbv[7]; o1.w = v; s += v * v;
        float* qr = g_qc + (size_t)(c0 + code) * DD;
        *(float4*)(qr + tc * 4) = o0;
        *(float4*)(qr + 64 + tc * 4) = o1;
        __nv_bfloat162* hb = g_ch + (size_t)(c0 + code) * 64;
        __nv_bfloat162* lb = g_cl + (size_t)(c0 + code) * 64;
        split_store4(hb, lb, tc * 2, o0);
        split_store4(hb, lb, 32 + tc * 2, o1);
        atomicAdd(&cn_s[code], s);
    }
    __syncthreads();
    if (tid < 64) g_cnorm[c0 + tid] = cn_s[tid];
}

// ---------------------------------------------------------------------------
// k_dist: bf16 hi/lo 3-term mma.sync scan; TOP-2 epilogue (measured 173us in
// R11/R12) + half-row-level flush limit via shfl.  Overflow safety: exact
// argmin's approx dist <= halfrow_best + 2*eps << MARGIN, so it is either
// kept or g_over forces the exact full scan.
// grid 128 = 64 row-blocks x 2 halves; 256 threads; 192KB smem.
// ---------------------------------------------------------------------------
__global__ __launch_bounds__(256, 1) void k_dist() {
    char* base = (char*)(((size_t)smem_raw + 1023) & ~(size_t)1023);
    char* sAh = base;
    char* sAl = base + 32768;
    char* sB[2][2] = {{base + 65536, base + 98304},
                      {base + 131072, base + 163840}};

    const int tid = threadIdx.x, lane = tid & 31, wid = tid >> 5;
    const int wm = wid & 3, wn = wid >> 2;
    const int rb = blockIdx.x >> 1, half = blockIdx.x & 1;
    const int ct0 = half * NT;

    copy_tile(sAh, g_zh + (size_t)rb * 8192, tid);
    copy_tile(sAl, g_zl + (size_t)rb * 8192, tid);
    copy_tile(sB[0][0], g_ch + (size_t)ct0 * 8192, tid);
    copy_tile(sB[0][1], g_cl + (size_t)ct0 * 8192, tid);
    cp_commit();
    cp_wait0();
    __syncthreads();

    const int mat = lane >> 3;
    const u32 uAh = (u32)__cvta_generic_to_shared(sAh);
    const u32 uAl = (u32)__cvta_generic_to_shared(sAl);
    u32 uB[2][2];
#pragma unroll
    for (int pb_ = 0; pb_ < 2; pb_++)
#pragma unroll
        for (int hl = 0; hl < 2; hl++)
            uB[pb_][hl] = (u32)__cvta_generic_to_shared(sB[pb_][hl]);

    u32 aRow[2], aChunkAdd = (u32)(mat >> 1);
#pragma unroll
    for (int f = 0; f < 2; f++)
        aRow[f] = (u32)(wm * 32 + f * 16 + (lane & 7) + ((mat & 1) << 3));
    u32 bRow[4], bChunkAdd = (u32)(mat & 1);
#pragma unroll
    for (int p = 0; p < 4; p++)
        bRow[p] = (u32)(wn * 64 + p * 16 + (lane & 7) + ((mat >> 1) << 3));

    // per-slot state: top-2 + evmin of everything else
    float zn_s[4], t1v[4], t2v[4], evm[4];
    int i1v[4], i2v[4];
#pragma unroll
    for (int s = 0; s < 4; s++) {
        int row = rb * 128 + wm * 32 + (s >> 1) * 16 + (s & 1) * 8 + (lane >> 2);
        zn_s[s] = g_zn[row];
        t1v[s] = 3.4e38f; t2v[s] = 3.4e38f; evm[s] = 3.4e38f;
        i1v[s] = 0; i2v[s] = 0;
    }

    for (int t = 0; t < NT; t++) {
        int pbuf = t & 1;
        if (t + 1 < NT) {
            copy_tile(sB[pbuf ^ 1][0], g_ch + (size_t)(ct0 + t + 1) * 8192, tid);
            copy_tile(sB[pbuf ^ 1][1], g_cl + (size_t)(ct0 + t + 1) * 8192, tid);
            cp_commit();
        }

        float acc[2][8][4];
#pragma unroll
        for (int f = 0; f < 2; f++)
#pragma unroll
            for (int nf = 0; nf < 8; nf++)
#pragma unroll
                for (int c = 0; c < 4; c++) acc[f][nf][c] = 0.f;

        u32 curBh = uB[pbuf][0], curBl = uB[pbuf][1];
#pragma unroll
        for (int ks = 0; ks < 8; ks++) {
            u32 ah[2][4], al[2][4];
#pragma unroll
            for (int f = 0; f < 2; f++) {
                u32 off = (aRow[f] << 8) |
                          ((((u32)(ks * 2) + aChunkAdd) ^ (aRow[f] & 7u)) << 4);
                LDSM4(ah[f], uAh + off);
                LDSM4(al[f], uAl + off);
            }
            u32 bh[4][4], bl[4][4];
#pragma unroll
            for (int p = 0; p < 4; p++) {
                u32 off = (bRow[p] << 8) |
                          ((((u32)(ks * 2) + bChunkAdd) ^ (bRow[p] & 7u)) << 4);
                LDSM4(bh[p], curBh + off);
                LDSM4(bl[p], curBl + off);
            }
#pragma unroll
            for (int f = 0; f < 2; f++)
#pragma unroll
                for (int nf = 0; nf < 8; nf++) {
                    int p = nf >> 1, q = (nf & 1) * 2;
                    MMA16816(acc[f][nf], ah[f], bh[p][q], bh[p][q + 1]);
                }
#pragma unroll
            for (int f = 0; f < 2; f++)
#pragma unroll
                for (int nf = 0; nf < 8; nf++) {
                    int p = nf >> 1, q = (nf & 1) * 2;
                    MMA16816(acc[f][nf], ah[f], bl[p][q], bl[p][q + 1]);
                }
#pragma unroll
            for (int f = 0; f < 2; f++)
#pragma unroll
                for (int nf = 0; nf < 8; nf++) {
                    int p = nf >> 1, q = (nf & 1) * 2;
                    MMA16816(acc[f][nf], al[f], bh[p][q], bh[p][q + 1]);
                }
        }

        // epilogue: dist = ||z||^2 + ||c||^2 - 2*dot ; top-2 + evmin capture
        int code0 = half * 4096 + t * 128 + wn * 64;
#pragma unroll
        for (int nf = 0; nf < 8; nf++) {
            int cb = code0 + nf * 8 + (lane & 3) * 2;
            float cn0 = __ldg(&g_cnorm[cb]);
            float cn1 = __ldg(&g_cnorm[cb + 1]);
#pragma unroll
            for (int s = 0; s < 4; s++) {
                int f = s >> 1, g = s & 1;
                float dv[2];
                dv[0] = (zn_s[s] + cn0) - 2.0f * acc[f][nf][g * 2];
                dv[1] = (zn_s[s] + cn1) - 2.0f * acc[f][nf][g * 2 + 1];
#pragma unroll
                for (int j = 0; j < 2; j++) {
                    float d = dv[j];
                    int idx = cb + j;
                    if (d < t2v[s]) {
                        evm[s] = fminf(evm[s], t2v[s]);
                        if (d < t1v[s]) {
                            t2v[s] = t1v[s]; i2v[s] = i1v[s];
                            t1v[s] = d; i1v[s] = idx;
                        } else {
                            t2v[s] = d; i2v[s] = idx;
                        }
                    } else {
                        evm[s] = fminf(evm[s], d);
                    }
                }
            }
        }

        if (t + 1 < NT) { cp_wait0(); __syncthreads(); }
    }

    // flush: half-row-level best (min over the 4 lanes sharing this row) sets
    // the margin window for candidate-keep and the exact overflow test.
#pragma unroll
    for (int s = 0; s < 4; s++) {
        int row = rb * 128 + wm * 32 + (s >> 1) * 16 + (s & 1) * 8 + (lane >> 2);
        float rbv = fminf(t1v[s], __shfl_xor_sync(0xffffffffu, t1v[s], 1));
        rbv = fminf(rbv, __shfl_xor_sync(0xffffffffu, rbv, 2));
        float lim = rbv + MARGIN;
        int tmpi[2], n = 0;
        if (t1v[s] <= lim) tmpi[n++] = i1v[s];
        if (t2v[s] <= lim) tmpi[n++] = i2v[s];
        if (n) {
            int pos = atomicAdd(&g_candn[row], n);
            g_cand[row * 64 + pos] = tmpi[0];
            if (n == 2) g_cand[row * 64 + pos + 1] = tmpi[1];
        }
        if (evm[s] <= lim) g_over[row] = 1;
    }
}

// ---------------------------------------------------------------------------
// k_rescue: BLOCK per row (256 threads, measured 52us@p=0.15 in R13); exact
// fp32 over candidates, full scan if overflow; lowest-index tie-break.
// ---------------------------------------------------------------------------
static __device__ __forceinline__ float exact_dist(const float* z, int row, int code) {
    const float4* zr = (const float4*)(z + (size_t)row * DD);
    const float4* cr = (const float4*)(g_qc + (size_t)code * DD);
    float dot = 0.f;
#pragma unroll 8
    for (int i = 0; i < 32; i++) {
        float4 a = zr[i], b = cr[i];
        dot += a.x * b.x; dot += a.y * b.y; dot += a.z * b.z; dot += a.w * b.w;
    }
    return (g_zn[row] + g_cnorm[code]) - 2.0f * dot;
}

__global__ __launch_bounds__(256) void k_rescue(const float* __restrict__ z) {
    __shared__ ull skey[8];
    const int row = blockIdx.x;
    const int tid = threadIdx.x, lane = tid & 31, wid = tid >> 5;

    ull key = ~0ULL;
    if (g_over[row]) {
        for (int code = tid; code < KC; code += 256) {
            float d = exact_dist(z, row, code);
            unsigned ub = __float_as_uint(d);
            ub = (ub & 0x80000000u) ? ~ub : (ub | 0x80000000u);
            ull k = ((ull)ub << 32) | (unsigned)code;
            if (k < key) key = k;
        }
    } else {
        int n = g_candn[row];
        for (int i = tid; i < n; i += 256) {
            int code = g_cand[row * 64 + i];
            float d = exact_dist(z, row, code);
            unsigned ub = __float_as_uint(d);
            ub = (ub & 0x80000000u) ? ~ub : (ub | 0x80000000u);
            ull k = ((ull)ub << 32) | (unsigned)code;
            if (k < key) key = k;
        }
    }
#pragma unroll
    for (int o = 16; o; o >>= 1) {
        ull other = __shfl_xor_sync(0xffffffffu, key, o);
        if (other < key) key = other;
    }
    if (lane == 0) skey[wid] = key;
    __syncthreads();
    if (tid == 0) {
        ull best = skey[0];
#pragma unroll
        for (int i = 1; i < 8; i++) if (skey[i] < best) best = skey[i];
        int idx = (int)(best & 0xffffffffu);
        g_idx[row] = idx;
        atomicAdd(&g_counts[idx], 1.0f);
    }
}

// ---------------------------------------------------------------------------
// k_out: z_q = z + (qc[idx]-z); commit partial sums
// ---------------------------------------------------------------------------
__global__ __launch_bounds__(256) void k_out(const float* __restrict__ z,
                                             float* __restrict__ out) {
    __shared__ float credu[8];
    const int tid = threadIdx.x;
    const int n0 = blockIdx.x * 64;
    float csum = 0.f;
    {
        int r = n0 + (tid >> 2), part = tid & 3;
        int idxk = g_idx[r];
        const float4* qv = (const float4*)(g_qc + (size_t)idxk * DD) + part * 8;
        const float4* zv = (const float4*)(z + (size_t)r * DD) + part * 8;
        float4* ov = (float4*)(out + (size_t)r * DD) + part * 8;
#pragma unroll
        for (int i = 0; i < 8; i++) {
            float4 q = qv[i], zz = zv[i], o;
            float dx = q.x - zz.x, dy = q.y - zz.y, dz2 = q.z - zz.z, dw = q.w - zz.w;
            o.x = zz.x + dx; o.y = zz.y + dy; o.z = zz.z + dz2; o.w = zz.w + dw;
            ov[i] = o;
            csum += dx * dx; csum += dy * dy; csum += dz2 * dz2; csum += dw * dw;
        }
    }
#pragma unroll
    for (int o = 16; o; o >>= 1) csum += __shfl_xor_sync(0xffffffffu, csum, o);
    if ((tid & 31) == 0) credu[tid >> 5] = csum;
    __syncthreads();
    if (tid == 0) {
        float t = 0.f;
#pragma unroll
        for (int i = 0; i < 8; i++) t += credu[i];
        atomicAdd(&g_commit, t);
    }
}

// ---------------------------------------------------------------------------
// k_final: scalars
// ---------------------------------------------------------------------------
__global__ __launch_bounds__(256) void k_final(const float* __restrict__ ema,
                                               float* __restrict__ out,
                                               int out_size) {
    __shared__ float r1[8], r2[8];
    int tid = threadIdx.x;
    const float omd = 1.0f - 0.99f;
    float s1 = 0.f, s2 = 0.f;
    for (int k = tid; k < KC; k += 256) {
        float em = g_counts[k] * (1.0f / NR);
        s1 += em * logf(em + 1e-10f);
        float nu = ema[k] * 0.99f + em * omd;
        s2 += nu * logf(nu + 1e-10f);
    }
#pragma unroll
    for (int o = 16; o; o >>= 1) {
        s1 += __shfl_xor_sync(0xffffffffu, s1, o);
        s2 += __shfl_xor_sync(0xffffffffu, s2, o);
    }
    if ((tid & 31) == 0) { r1[tid >> 5] = s1; r2[tid >> 5] = s2; }
    __syncthreads();
    if (tid == 0) {
        float S1 = 0.f, S2 = 0.f;
#pragma unroll
        for (int i = 0; i < 8; i++) { S1 += r1[i]; S2 += r2[i]; }
        out[out_size - 3] = 1.25f * g_commit * (1.0f / ((float)NR * (float)DD));
        out[out_size - 2] = expf(-S1);
        out[out_size - 1] = -S2;
    }
}

// ---------------------------------------------------------------------------
extern "C" void kernel_launch(void* const* d_in, const int* in_sizes, int n_in,
                              void* d_out, int out_size) {
    const float* z   = (const float*)d_in[0];
    const float* emb = (const float*)d_in[1];
    const float* pw  = (const float*)d_in[2];
    const float* pb  = (const float*)d_in[3];
    const float* ema = (const float*)d_in[4];
    float* out = (float*)d_out;

    const int smem_proj = (16384 + 8192 + 64) * 4;   // 98560
    const int smem_dist = 196608 + 1024;             // 192KB + align
    cudaFuncSetAttribute(k_proj, cudaFuncAttributeMaxDynamicSharedMemorySize, smem_proj);
    cudaFuncSetAttribute(k_dist, cudaFuncAttributeMaxDynamicSharedMemorySize, smem_dist);

    k_prep<<<32, 256>>>(z);
    k_proj<<<KC / 64, 256, smem_proj>>>(emb, pw, pb);
    k_dist<<<128, 256, smem_dist>>>();
    k_rescue<<<NR, 256>>>(z);
    k_out<<<NR / 64, 256>>>(z, out);
    k_final<<<1, 256>>>(ema, out, out_size);
}

// round 15
// speedup vs baseline: 1.1864x; 1.1864x over previous
#include <cuda_runtime.h>
#include <cuda_bf16.h>
#include <math.h>

#define KC 8192
#define DD 128
#define NR 8192
#define NT 32            // 128-code tiles per half codebook
#define MARGIN 0.01f

typedef unsigned long long ull;
typedef unsigned int u32;

// ---- global scratch (static, no allocations) ----
__device__ float g_qc[KC * DD];
__device__ float g_cnorm[KC];
__device__ float g_zn[NR];
__device__ float g_counts[KC];
__device__ float g_commit;
__device__ int   g_candn[NR];
__device__ int   g_cand[NR * 64];
__device__ int   g_over[NR];
// linear bf16 hi/lo operands, row-major [8192][128]
__device__ __nv_bfloat162 g_zh[NR * 64];
__device__ __nv_bfloat162 g_zl[NR * 64];
__device__ __nv_bfloat162 g_ch[KC * 64];
__device__ __nv_bfloat162 g_cl[KC * 64];

extern __shared__ char smem_raw[];

// ---- asm helpers (sm_80-era, compile at compute_100) ----
static __device__ __forceinline__ void cp_commit() {
    asm volatile("cp.async.commit_group;");
}
static __device__ __forceinline__ void cp_wait0() {
    asm volatile("cp.async.wait_group 0;");
}
#define LDSM4(r, addr) \
    asm volatile("ldmatrix.sync.aligned.m8n8.x4.shared.b16 {%0,%1,%2,%3}, [%4];" \
        : "=r"((r)[0]), "=r"((r)[1]), "=r"((r)[2]), "=r"((r)[3]) : "r"(addr))
#define MMA16816(c, a, b0, b1) \
    asm volatile("mma.sync.aligned.m16n8k16.row.col.f32.bf16.bf16.f32 " \
        "{%0,%1,%2,%3},{%4,%5,%6,%7},{%8,%9},{%0,%1,%2,%3};" \
        : "+f"((c)[0]), "+f"((c)[1]), "+f"((c)[2]), "+f"((c)[3]) \
        : "r"((a)[0]), "r"((a)[1]), "r"((a)[2]), "r"((a)[3]), "r"(b0), "r"(b1))

// Copy one 32KB tile (128 rows x 256B) global->shared with chunk-XOR swizzle:
// 16B chunk c of row r lands at chunk (c ^ (r&7)) -> ldmatrix conflict-free.
static __device__ __forceinline__ void copy_tile(char* dst, const void* src, int tid) {
    u32 d = (u32)__cvta_generic_to_shared(dst);
    const char* s = (const char*)src;
#pragma unroll
    for (int i = 0; i < 8; i++) {
        int cid = tid + i * 256;
        u32 off = (u32)cid << 4;
        u32 row = off >> 8;
        u32 ch = (off >> 4) & 15u;
        u32 doff = (row << 8) | (((ch ^ (row & 7u)) & 15u) << 4);
        asm volatile("cp.async.cg.shared.global [%0], [%1], 16;"
                     :: "r"(d + doff), "l"(s + off));
    }
}

static __device__ __forceinline__ void split_store4(__nv_bfloat162* hb, __nv_bfloat162* lb,
                                                    int base2, float4 v) {
    __nv_bfloat16 h0 = __float2bfloat16(v.x), h1 = __float2bfloat16(v.y);
    __nv_bfloat16 h2 = __float2bfloat16(v.z), h3 = __float2bfloat16(v.w);
    __nv_bfloat162 hp0; hp0.x = h0; hp0.y = h1;
    __nv_bfloat162 hp1; hp1.x = h2; hp1.y = h3;
    __nv_bfloat162 lp0, lp1;
    lp0.x = __float2bfloat16(v.x - __bfloat162float(h0));
    lp0.y = __float2bfloat16(v.y - __bfloat162float(h1));
    lp1.x = __float2bfloat16(v.z - __bfloat162float(h2));
    lp1.y = __float2bfloat16(v.w - __bfloat162float(h3));
    hb[base2] = hp0; hb[base2 + 1] = hp1;
    lb[base2] = lp0; lb[base2 + 1] = lp1;
}

// ---------------------------------------------------------------------------
// k_prep: z -> bf16 hi/lo, exact fp32 row norms; zero per-run state.
// ---------------------------------------------------------------------------
__global__ __launch_bounds__(256) void k_prep(const float* __restrict__ z) {
    int row = blockIdx.x * 256 + threadIdx.x;
    g_candn[row] = 0; g_over[row] = 0; g_counts[row] = 0.f;
    if (row == 0) g_commit = 0.f;
    const float4* zr = (const float4*)(z + (size_t)row * DD);
    float s = 0.f;
#pragma unroll 8
    for (int i = 0; i < 32; i++) {
        float4 v = zr[i];
        s += v.x * v.x; s += v.y * v.y; s += v.z * v.z; s += v.w * v.w;
        split_store4(g_zh + row * 64, g_zl + row * 64, i * 2, v);
    }
    g_zn[row] = s;
}

// ---------------------------------------------------------------------------
// k_proj: qc = emb @ pw^T + pb ; cnorm ; bf16 hi/lo emit.
// ---------------------------------------------------------------------------
__global__ __launch_bounds__(256) void k_proj(const float* __restrict__ emb,
                                              const float* __restrict__ pw,
                                              const float* __restrict__ pb) {
    float* pwT = (float*)smem_raw;
    float* ebT = pwT + 16384;
    float* cn_s = ebT + 8192;
    const int tid = threadIdx.x;
    const int c0 = blockIdx.x * 64;
    if (tid < 64) cn_s[tid] = 0.f;
    {
        int n = tid & 127, h = tid >> 7;
        const float4* pr = (const float4*)(pw + (size_t)n * DD) + h * 16;
#pragma unroll
        for (int i = 0; i < 16; i++) {
            float4 v = pr[i];
            int k = (h * 16 + i) * 4;
            pwT[(k + 0) * 128 + n] = v.x; pwT[(k + 1) * 128 + n] = v.y;
            pwT[(k + 2) * 128 + n] = v.z; pwT[(k + 3) * 128 + n] = v.w;
        }
    }
    {
        int c = tid & 63, h = tid >> 6;
        const float4* er = (const float4*)(emb + (size_t)(c0 + c) * DD) + h * 8;
#pragma unroll
        for (int i = 0; i < 8; i++) {
            float4 v = er[i];
            int k = (h * 8 + i) * 4;
            ebT[(k + 0) * 64 + c] = v.x; ebT[(k + 1) * 64 + c] = v.y;
            ebT[(k + 2) * 64 + c] = v.z; ebT[(k + 3) * 64 + c] = v.w;
        }
    }
    __syncthreads();
    const int rg = tid >> 4, tc = tid & 15;
    float acc[4][8];
#pragma unroll
    for (int i = 0; i < 4; i++)
#pragma unroll
        for (int j = 0; j < 8; j++) acc[i][j] = 0.f;
#pragma unroll 4
    for (int k = 0; k < DD; k++) {
        float4 a = *(const float4*)(ebT + k * 64 + rg * 4);
        float4 b0 = *(const float4*)(pwT + k * 128 + tc * 4);
        float4 b1 = *(const float4*)(pwT + k * 128 + 64 + tc * 4);
        float av[4] = {a.x, a.y, a.z, a.w};
        float bv[8] = {b0.x, b0.y, b0.z, b0.w, b1.x, b1.y, b1.z, b1.w};
#pragma unroll
        for (int i = 0; i < 4; i++)
#pragma unroll
            for (int j = 0; j < 8; j++) acc[i][j] += av[i] * bv[j];
    }
    float pbv[8];
#pragma unroll
    for (int j = 0; j < 8; j++)
        pbv[j] = pb[(j < 4) ? (tc * 4 + j) : (64 + tc * 4 + (j - 4))];
#pragma unroll
    for (int i = 0; i < 4; i++) {
        int code = rg * 4 + i;
        float s = 0.f, v;
        float4 o0, o1;
        v = acc[i][0] + pbv[0]; o0.x = v; s += v * v;
        v = acc[i][1] + pbv[1]; o0.y = v; s += v * v;
        v = acc[i][2] + pbv[2]; o0.z = v; s += v * v;
        v = acc[i][3] + pbv[3]; o0.w = v; s += v * v;
        v = acc[i][4] + pbv[4]; o1.x = v; s += v * v;
        v = acc[i][5] + pbv[5]; o1.y = v; s += v * v;
        v = acc[i][6] + pbv[6]; o1.z = v; s += v * v;
        v = acc[i][7] + pbv[7]; o1.w = v; s += v * v;
        float* qr = g_qc + (size_t)(c0 + code) * DD;
        *(float4*)(qr + tc * 4) = o0;
        *(float4*)(qr + 64 + tc * 4) = o1;
        __nv_bfloat162* hb = g_ch + (size_t)(c0 + code) * 64;
        __nv_bfloat162* lb = g_cl + (size_t)(c0 + code) * 64;
        split_store4(hb, lb, tc * 2, o0);
        split_store4(hb, lb, 32 + tc * 2, o1);
        atomicAdd(&cn_s[code], s);
    }
    __syncthreads();
    if (tid < 64) g_cnorm[c0 + tid] = cn_s[tid];
}

// ---------------------------------------------------------------------------
// k_dist: R13's measured-good top-4 capture mainloop VERBATIM; only the flush
// changes: candidate-keep and overflow compare against the ROW-level best
// (min of tk[s][0] over the 4 lanes sharing the row, via 2 shfl_xor) instead
// of the slot best.  rowbest <= slotbest -> strictly fewer candidates AND
// strictly fewer overflow fires than R13; capacity stays 4 (R14 showed
// capacity 2 is the failure mode).
// ---------------------------------------------------------------------------
__global__ __launch_bounds__(256, 1) void k_dist() {
    char* base = (char*)(((size_t)smem_raw + 1023) & ~(size_t)1023);
    char* sAh = base;
    char* sAl = base + 32768;
    char* sB[2][2] = {{base + 65536, base + 98304},
                      {base + 131072, base + 163840}};

    const int tid = threadIdx.x, lane = tid & 31, wid = tid >> 5;
    const int wm = wid & 3, wn = wid >> 2;
    const int rb = blockIdx.x >> 1, half = blockIdx.x & 1;
    const int ct0 = half * NT;

    copy_tile(sAh, g_zh + (size_t)rb * 8192, tid);
    copy_tile(sAl, g_zl + (size_t)rb * 8192, tid);
    copy_tile(sB[0][0], g_ch + (size_t)ct0 * 8192, tid);
    copy_tile(sB[0][1], g_cl + (size_t)ct0 * 8192, tid);
    cp_commit();
    cp_wait0();
    __syncthreads();

    const int mat = lane >> 3;
    const u32 uAh = (u32)__cvta_generic_to_shared(sAh);
    const u32 uAl = (u32)__cvta_generic_to_shared(sAl);
    u32 uB[2][2];
#pragma unroll
    for (int pb_ = 0; pb_ < 2; pb_++)
#pragma unroll
        for (int hl = 0; hl < 2; hl++)
            uB[pb_][hl] = (u32)__cvta_generic_to_shared(sB[pb_][hl]);

    u32 aRow[2], aChunkAdd = (u32)(mat >> 1);
#pragma unroll
    for (int f = 0; f < 2; f++)
        aRow[f] = (u32)(wm * 32 + f * 16 + (lane & 7) + ((mat & 1) << 3));
    u32 bRow[4], bChunkAdd = (u32)(mat & 1);
#pragma unroll
    for (int p = 0; p < 4; p++)
        bRow[p] = (u32)(wn * 64 + p * 16 + (lane & 7) + ((mat >> 1) << 3));

    // per-slot state: sorted top-4 (c0<=c1<=c2<=c3) + evmin of everything lost
    float zn_s[4], tk[4][4], evmin[4];
    int ti[4][4];
#pragma unroll
    for (int s = 0; s < 4; s++) {
        int row = rb * 128 + wm * 32 + (s >> 1) * 16 + (s & 1) * 8 + (lane >> 2);
        zn_s[s] = g_zn[row];
        evmin[s] = 3.4e38f;
#pragma unroll
        for (int q = 0; q < 4; q++) { tk[s][q] = 3.4e38f; ti[s][q] = 0; }
    }

    for (int t = 0; t < NT; t++) {
        int pbuf = t & 1;
        if (t + 1 < NT) {
            copy_tile(sB[pbuf ^ 1][0], g_ch + (size_t)(ct0 + t + 1) * 8192, tid);
            copy_tile(sB[pbuf ^ 1][1], g_cl + (size_t)(ct0 + t + 1) * 8192, tid);
            cp_commit();
        }

        float acc[2][8][4];
#pragma unroll
        for (int f = 0; f < 2; f++)
#pragma unroll
            for (int nf = 0; nf < 8; nf++)
#pragma unroll
                for (int c = 0; c < 4; c++) acc[f][nf][c] = 0.f;

        u32 curBh = uB[pbuf][0], curBl = uB[pbuf][1];
#pragma unroll
        for (int ks = 0; ks < 8; ks++) {
            u32 ah[2][4], al[2][4];
#pragma unroll
            for (int f = 0; f < 2; f++) {
                u32 off = (aRow[f] << 8) |
                          ((((u32)(ks * 2) + aChunkAdd) ^ (aRow[f] & 7u)) << 4);
                LDSM4(ah[f], uAh + off);
                LDSM4(al[f], uAl + off);
            }
            u32 bh[4][4], bl[4][4];
#pragma unroll
            for (int p = 0; p < 4; p++) {
                u32 off = (bRow[p] << 8) |
                          ((((u32)(ks * 2) + bChunkAdd) ^ (bRow[p] & 7u)) << 4);
                LDSM4(bh[p], curBh + off);
                LDSM4(bl[p], curBl + off);
            }
#pragma unroll
            for (int f = 0; f < 2; f++)
#pragma unroll
                for (int nf = 0; nf < 8; nf++) {
                    int p = nf >> 1, q = (nf & 1) * 2;
                    MMA16816(acc[f][nf], ah[f], bh[p][q], bh[p][q + 1]);
                }
#pragma unroll
            for (int f = 0; f < 2; f++)
#pragma unroll
                for (int nf = 0; nf < 8; nf++) {
                    int p = nf >> 1, q = (nf & 1) * 2;
                    MMA16816(acc[f][nf], ah[f], bl[p][q], bl[p][q + 1]);
                }
#pragma unroll
            for (int f = 0; f < 2; f++)
#pragma unroll
                for (int nf = 0; nf < 8; nf++) {
                    int p = nf >> 1, q = (nf & 1) * 2;
                    MMA16816(acc[f][nf], al[f], bh[p][q], bh[p][q + 1]);
                }
        }

        // epilogue: dist = ||z||^2+||c||^2-2*dot; top-4 insert / evmin reject
        int code0 = half * 4096 + t * 128 + wn * 64;
#pragma unroll
        for (int nf = 0; nf < 8; nf++) {
            int cb = code0 + nf * 8 + (lane & 3) * 2;
            float cn0 = __ldg(&g_cnorm[cb]);
            float cn1 = __ldg(&g_cnorm[cb + 1]);
#pragma unroll
            for (int s = 0; s < 4; s++) {
                int f = s >> 1, g = s & 1;
                float dv[2];
                dv[0] = (zn_s[s] + cn0) - 2.0f * acc[f][nf][g * 2];
                dv[1] = (zn_s[s] + cn1) - 2.0f * acc[f][nf][g * 2 + 1];
#pragma unroll
                for (int j = 0; j < 2; j++) {
                    float d = dv[j];
                    int idx = cb + j;
                    if (d < tk[s][3]) {
                        evmin[s] = fminf(evmin[s], tk[s][3]);  // evicted
                        if (d < tk[s][0]) {
                            tk[s][3] = tk[s][2]; ti[s][3] = ti[s][2];
                            tk[s][2] = tk[s][1]; ti[s][2] = ti[s][1];
                            tk[s][1] = tk[s][0]; ti[s][1] = ti[s][0];
                            tk[s][0] = d; ti[s][0] = idx;
                        } else if (d < tk[s][1]) {
                            tk[s][3] = tk[s][2]; ti[s][3] = ti[s][2];
                            tk[s][2] = tk[s][1]; ti[s][2] = ti[s][1];
                            tk[s][1] = d; ti[s][1] = idx;
                        } else if (d < tk[s][2]) {
                            tk[s][3] = tk[s][2]; ti[s][3] = ti[s][2];
                            tk[s][2] = d; ti[s][2] = idx;
                        } else {
                            tk[s][3] = d; ti[s][3] = idx;
                        }
                    } else {
                        evmin[s] = fminf(evmin[s], d);         // rejected
                    }
                }
            }
        }

        if (t + 1 < NT) { cp_wait0(); __syncthreads(); }
    }

    // flush: ROW-level best over the 4 lanes sharing this row sets the window
#pragma unroll
    for (int s = 0; s < 4; s++) {
        int row = rb * 128 + wm * 32 + (s >> 1) * 16 + (s & 1) * 8 + (lane >> 2);
        float rbv = fminf(tk[s][0], __shfl_xor_sync(0xffffffffu, tk[s][0], 1));
        rbv = fminf(rbv, __shfl_xor_sync(0xffffffffu, rbv, 2));
        float lim = rbv + MARGIN;
        int tmpi[4], n = 0;
#pragma unroll
        for (int q = 0; q < 4; q++)
            if (tk[s][q] <= lim) tmpi[n++] = ti[s][q];
        if (n) {
            int pos = atomicAdd(&g_candn[row], n);
            for (int q = 0; q < n; q++) g_cand[row * 64 + pos + q] = tmpi[q];
        }
        if (evmin[s] <= lim) g_over[row] = 1;
    }
}

// ---------------------------------------------------------------------------
// k_rescue: BLOCK per row; exact fp32 over candidates (full scan if overflow),
// lowest-index tie-break; then fused gather z_q + counts + commit partial.
// ---------------------------------------------------------------------------
static __device__ __forceinline__ float exact_dist(const float* z, int row, int code) {
    const float4* zr = (const float4*)(z + (size_t)row * DD);
    const float4* cr = (const float4*)(g_qc + (size_t)code * DD);
    float dot = 0.f;
#pragma unroll 8
    for (int i = 0; i < 32; i++) {
        float4 a = zr[i], b = cr[i];
        dot += a.x * b.x; dot += a.y * b.y; dot += a.z * b.z; dot += a.w * b.w;
    }
    return (g_zn[row] + g_cnorm[code]) - 2.0f * dot;
}

__global__ __launch_bounds__(256) void k_rescue(const float* __restrict__ z,
                                                float* __restrict__ out) {
    __shared__ ull skey[8];
    __shared__ int sidx;
    __shared__ float scsum;
    const int row = blockIdx.x;
    const int tid = threadIdx.x, lane = tid & 31, wid = tid >> 5;

    ull key = ~0ULL;
    if (g_over[row]) {
        for (int code = tid; code < KC; code += 256) {
            float d = exact_dist(z, row, code);
            unsigned ub = __float_as_uint(d);
            ub = (ub & 0x80000000u) ? ~ub : (ub | 0x80000000u);
            ull k = ((ull)ub << 32) | (unsigned)code;
            if (k < key) key = k;
        }
    } else {
        int n = g_candn[row];
        for (int i = tid; i < n; i += 256) {
            int code = g_cand[row * 64 + i];
            float d = exact_dist(z, row, code);
            unsigned ub = __float_as_uint(d);
            ub = (ub & 0x80000000u) ? ~ub : (ub | 0x80000000u);
            ull k = ((ull)ub << 32) | (unsigned)code;
            if (k < key) key = k;
        }
    }
#pragma unroll
    for (int o = 16; o; o >>= 1) {
        ull other = __shfl_xor_sync(0xffffffffu, key, o);
        if (other < key) key = other;
    }
    if (lane == 0) skey[wid] = key;
    __syncthreads();
    if (tid == 0) {
        ull best = skey[0];
#pragma unroll
        for (int i = 1; i < 8; i++) if (skey[i] < best) best = skey[i];
        int idx = (int)(best & 0xffffffffu);
        sidx = idx;
        atomicAdd(&g_counts[idx], 1.0f);
    }
    __syncthreads();

    // fused gather: z_q = z + (qc[idx]-z); commit partial via warp 0
    if (wid == 0) {
        int idx = sidx;
        const float4* qv = (const float4*)(g_qc + (size_t)idx * DD) + lane;
        const float4* zv = (const float4*)(z + (size_t)row * DD) + lane;
        float4* ov = (float4*)(out + (size_t)row * DD) + lane;
        float4 q = *qv, zz = *zv, o;
        float dx = q.x - zz.x, dy = q.y - zz.y, dz2 = q.z - zz.z, dw = q.w - zz.w;
        o.x = zz.x + dx; o.y = zz.y + dy; o.z = zz.z + dz2; o.w = zz.w + dw;
        *ov = o;
        float csum = dx * dx + dy * dy + dz2 * dz2 + dw * dw;
#pragma unroll
        for (int o2 = 16; o2; o2 >>= 1) csum += __shfl_xor_sync(0xffffffffu, csum, o2);
        if (lane == 0) scsum = csum;
    }
    __syncthreads();
    if (tid == 0) atomicAdd(&g_commit, scsum);
}

// ---------------------------------------------------------------------------
// k_final: scalars
// ---------------------------------------------------------------------------
__global__ __launch_bounds__(256) void k_final(const float* __restrict__ ema,
                                               float* __restrict__ out,
                                               int out_size) {
    __shared__ float r1[8], r2[8];
    int tid = threadIdx.x;
    const float omd = 1.0f - 0.99f;
    float s1 = 0.f, s2 = 0.f;
    for (int k = tid; k < KC; k += 256) {
        float em = g_counts[k] * (1.0f / NR);
        s1 += em * logf(em + 1e-10f);
        float nu = ema[k] * 0.99f + em * omd;
        s2 += nu * logf(nu + 1e-10f);
    }
#pragma unroll
    for (int o = 16; o; o >>= 1) {
        s1 += __shfl_xor_sync(0xffffffffu, s1, o);
        s2 += __shfl_xor_sync(0xffffffffu, s2, o);
    }
    if ((tid & 31) == 0) { r1[tid >> 5] = s1; r2[tid >> 5] = s2; }
    __syncthreads();
    if (tid == 0) {
        float S1 = 0.f, S2 = 0.f;
#pragma unroll
        for (int i = 0; i < 8; i++) { S1 += r1[i]; S2 += r2[i]; }
        out[out_size - 3] = 1.25f * g_commit * (1.0f / ((float)NR * (float)DD));
        out[out_size - 2] = expf(-S1);
        out[out_size - 1] = -S2;
    }
}

// ---------------------------------------------------------------------------
extern "C" void kernel_launch(void* const* d_in, const int* in_sizes, int n_in,
                              void* d_out, int out_size) {
    const float* z   = (const float*)d_in[0];
    const float* emb = (const float*)d_in[1];
    const float* pw  = (const float*)d_in[2];
    const float* pb  = (const float*)d_in[3];
    const float* ema = (const float*)d_in[4];
    float* out = (float*)d_out;

    const int smem_proj = (16384 + 8192 + 64) * 4;   // 98560
    const int smem_dist = 196608 + 1024;             // 192KB + align
    cudaFuncSetAttribute(k_proj, cudaFuncAttributeMaxDynamicSharedMemorySize, smem_proj);
    cudaFuncSetAttribute(k_dist, cudaFuncAttributeMaxDynamicSharedMemorySize, smem_dist);

    k_prep<<<32, 256>>>(z);
    k_proj<<<KC / 64, 256, smem_proj>>>(emb, pw, pb);
    k_dist<<<128, 256, smem_dist>>>();
    k_rescue<<<NR, 256>>>(z, out);
    k_final<<<1, 256>>>(ema, out, out_size);
}